// round 15
// baseline (speedup 1.0000x reference)
#include <cuda_runtime.h>

// LS_loss: single kernel, multi-wave grid, SINGLE-SPINNER finalize.
//
// Shapes: input, img_mean : (32, 4, 512, 512) fp32, contiguous.
// 128 channels x 262144 floats (= 65536 float4 each), 32 blocks per channel.
//
// Per channel (N = 262144):
//   Hea = 0.5*(1+tanh(x/0.05))
//   A = sum(Hea), B1 = sum(Hea*img), S = sum(img), Q = sum(img^2)
//   c1 = B1/(A+eps), c2 = (S-B1)/(N-A+eps)
//   chan = Q - 2*(c1*B1 + c2*(S-B1)) + c1^2*A + c2^2*(N-A)
//   out  = sum_chan / (B*C*H*W)
//
// Structure:
//  - 4096 blocks x 128 threads (the R11 pass1 geometry, measured at ~6.6TB/s).
//    GRP=4 front-batched LDG.128 (MLP~8/thread).
//  - Per-channel 128B-strided arrival counters (32 arrivals each, parallel
//    across L2 slices, self-reset by the channel-last block). Channel-last
//    bumps MONOTONIC g_done (128 bumps per launch; never reset -> graph-
//    replay safe via wrap-proof "g_done - phase0 >= 128" test).
//  - ONLY block 0 spins (nanosleep) for all 128 channels, then finalizes:
//    thread t = channel t gathers its 32 partials (fixed order), closed
//    form, deterministic 128-lane reduce, writes out[0].
//  - Multi-wave safe: one spinner cannot starve the grid (every SM has many
//    other block slots cycling). Single kernel -> safe under ncu replay.
//  - phase0 is sampled by block 0 (wave 1) before its mainloop; the first
//    g_done bump requires a full channel (32 blocks) to finish, >=10us
//    later, so phase0 always reads the pre-launch value.

#define N_PER_CH    262144
#define F4_PER_CH   65536
#define BLKS_PER_CH 32
#define NBLOCKS     (128 * BLKS_PER_CH)        // 4096
#define F4_PER_BLK  (F4_PER_CH / BLKS_PER_CH)  // 2048
#define THREADS     128
#define F4_PER_THR  (F4_PER_BLK / THREADS)     // 16
#define GRP         4
#define NGRP        (F4_PER_THR / GRP)         // 4
#define LS_EPS      1e-4f
#define INV_EPISON  20.0f
#define CTR_STRIDE  32                          // 128 B between counters

static __device__ float4 g_partials[NBLOCKS];                 // 64 KB
static __device__ unsigned int g_arrive_ch[128 * CTR_STRIDE]; // strided counters
static __device__ unsigned int g_done = 0;                    // MONOTONIC

__device__ __forceinline__ float tanh_fast(float x) {
    float y;
    asm("tanh.approx.f32 %0, %1;" : "=f"(y) : "f"(x));
    return y;
}

__device__ __forceinline__ void accum1(float x, float m,
                                       float& sH, float& sHI, float& sI, float& sI2) {
    float h = fmaf(0.5f, tanh_fast(INV_EPISON * x), 0.5f);
    sH  += h;
    sHI  = fmaf(h, m, sHI);
    sI  += m;
    sI2  = fmaf(m, m, sI2);
}

__device__ __forceinline__ float4 ldcg4(const float4* p) {
    float4 v;
    asm volatile("ld.global.cg.v4.f32 {%0,%1,%2,%3}, [%4];"
                 : "=f"(v.x), "=f"(v.y), "=f"(v.z), "=f"(v.w) : "l"(p));
    return v;
}

__global__ void __launch_bounds__(THREADS)
ls_loss_one(const float4* __restrict__ inp, const float4* __restrict__ img,
            float* __restrict__ out)
{
    const int b  = blockIdx.x;
    const int t  = threadIdx.x;
    const int ch = b / BLKS_PER_CH;
    const long base = (long)b * F4_PER_BLK + t;

    // Block 0: sample the monotonic done-count before any work. The first
    // bump this launch needs a whole channel (32 blocks) to finish, so this
    // read always precedes it.
    unsigned int phase0 = 0;
    if (b == 0 && t == 0)
        asm volatile("ld.global.u32 %0, [%1];" : "=r"(phase0) : "l"(&g_done));

    float sH = 0.f, sHI = 0.f, sI = 0.f, sI2 = 0.f;

    #pragma unroll
    for (int g = 0; g < NGRP; g++) {
        float4 x[GRP], m[GRP];
        #pragma unroll
        for (int j = 0; j < GRP; j++) {          // front-batch 8 LDG.128
            const long idx = base + (long)(g * GRP + j) * THREADS;
            x[j] = __ldcs(&inp[idx]);
            m[j] = __ldcs(&img[idx]);
        }
        #pragma unroll
        for (int j = 0; j < GRP; j++) {
            accum1(x[j].x, m[j].x, sH, sHI, sI, sI2);
            accum1(x[j].y, m[j].y, sH, sHI, sI, sI2);
            accum1(x[j].z, m[j].z, sH, sHI, sI, sI2);
            accum1(x[j].w, m[j].w, sH, sHI, sI, sI2);
        }
    }

    // Deterministic warp tree reduce
    #pragma unroll
    for (int o = 16; o > 0; o >>= 1) {
        sH  += __shfl_down_sync(0xFFFFFFFFu, sH,  o);
        sHI += __shfl_down_sync(0xFFFFFFFFu, sHI, o);
        sI  += __shfl_down_sync(0xFFFFFFFFu, sI,  o);
        sI2 += __shfl_down_sync(0xFFFFFFFFu, sI2, o);
    }

    __shared__ float4 sm[THREADS / 32];
    const int warp = t >> 5, lane = t & 31;
    if (lane == 0) sm[warp] = make_float4(sH, sHI, sI, sI2);
    __syncthreads();

    if (t == 0) {
        float4 tot = sm[0];
        #pragma unroll
        for (int w = 1; w < THREADS / 32; w++) {
            float4 v = sm[w];
            tot.x += v.x; tot.y += v.y; tot.z += v.z; tot.w += v.w;
        }
        g_partials[b] = tot;
        __threadfence();                          // publish partial before arrive
        unsigned int prev = atomicAdd(&g_arrive_ch[ch * CTR_STRIDE], 1u);
        if (prev == BLKS_PER_CH - 1) {
            // channel complete: self-reset its counter, bump monotonic g_done
            *(volatile unsigned int*)&g_arrive_ch[ch * CTR_STRIDE] = 0u;
            __threadfence();
            atomicAdd(&g_done, 1u);
        }
    }

    if (b != 0) return;                           // everyone else exits; no spin

    // ---- block 0: sole spinner, then full finalize ----
    if (t == 0) {
        unsigned int v;
        do {
            asm volatile("ld.global.acquire.gpu.u32 %0, [%1];"
                         : "=r"(v) : "l"(&g_done));
            if (v - phase0 < 128u) __nanosleep(256);
        } while (v - phase0 < 128u);
    }
    __syncthreads();
    __threadfence();                              // order partial reads

    // thread t owns channel t: 32 partials, fixed order (64 KB total gather)
    float A = 0.f, B1 = 0.f, S = 0.f, Q = 0.f;
    #pragma unroll
    for (int i = 0; i < BLKS_PER_CH; i++) {
        float4 v = ldcg4(&g_partials[t * BLKS_PER_CH + i]);
        A += v.x; B1 += v.y; S += v.z; Q += v.w;
    }

    const float Nf = (float)N_PER_CH;
    const float s3 = Nf - A;
    const float c1 = B1 / (A + LS_EPS);
    const float c2 = (S - B1) / (s3 + LS_EPS);
    float chan = Q - 2.f * (c1 * B1 + c2 * (S - B1))
               + c1 * c1 * A + c2 * c2 * s3;

    #pragma unroll
    for (int o = 16; o > 0; o >>= 1)
        chan += __shfl_down_sync(0xFFFFFFFFu, chan, o);

    __shared__ float smc[4];
    if (lane == 0) smc[warp] = chan;
    __syncthreads();

    if (t == 0) {
        out[0] = (smc[0] + smc[1] + smc[2] + smc[3])
               / (float)(32 * 4 * N_PER_CH);
    }
}

extern "C" void kernel_launch(void* const* d_in, const int* in_sizes, int n_in,
                              void* d_out, int out_size)
{
    const float4* inp = (const float4*)d_in[0];   // 'input'
    const float4* img = (const float4*)d_in[1];   // 'img_mean'
    ls_loss_one<<<NBLOCKS, THREADS>>>(inp, img, (float*)d_out);
}

// round 16
// speedup vs baseline: 1.0756x; 1.0756x over previous
#include <cuda_runtime.h>

// LS_loss: two-kernel champion (R11 structure); pass2 gather parallelized.
//
// Shapes: input, img_mean : (32, 4, 512, 512) fp32, contiguous.
// 128 channels x 262144 floats (= 65536 float4 each), 32 blocks per channel.
//
// Per channel (N = 262144):
//   Hea = 0.5*(1+tanh(x/0.05))
//   A = sum(Hea), B1 = sum(Hea*img), S = sum(img), Q = sum(img^2)
//   c1 = B1/(A+eps), c2 = (S-B1)/(N-A+eps)
//   chan = Q - 2*(c1*B1 + c2*(S-B1)) + c1^2*A + c2^2*(N-A)
//   out  = sum_chan / (B*C*H*W)
//
// pass1: 4096 blocks x 128 threads; 16 float4-pairs/thread in 4 front-batched
//        groups (MLP~8); fence + programmatic-completion trigger per block.
// pass2: PDL launch, 512 threads: 4 threads per channel, each front-batches
//        8 partial loads (MLP 8), shuffle-combine, closed form, fixed-order
//        final reduce. Cuts the post-sync gather from ~2us to ~0.5us.

#define N_PER_CH    262144
#define F4_PER_CH   65536
#define BLKS_PER_CH 32
#define NBLOCKS     (128 * BLKS_PER_CH)        // 4096
#define F4_PER_BLK  (F4_PER_CH / BLKS_PER_CH)  // 2048
#define THREADS     128
#define F4_PER_THR  (F4_PER_BLK / THREADS)     // 16
#define GRP         4
#define NGRP        (F4_PER_THR / GRP)         // 4
#define LS_EPS      1e-4f
#define INV_EPISON  20.0f

static __device__ float4 g_partials[NBLOCKS];   // 64 KB scratch

__device__ __forceinline__ float tanh_fast(float x) {
    float y;
    asm("tanh.approx.f32 %0, %1;" : "=f"(y) : "f"(x));
    return y;
}

__device__ __forceinline__ void accum1(float x, float m,
                                       float& sH, float& sHI, float& sI, float& sI2) {
    float h = fmaf(0.5f, tanh_fast(INV_EPISON * x), 0.5f);
    sH  += h;
    sHI  = fmaf(h, m, sHI);
    sI  += m;
    sI2  = fmaf(m, m, sI2);
}

__device__ __forceinline__ float4 ldcg4(const float4* p) {
    float4 v;
    asm volatile("ld.global.cg.v4.f32 {%0,%1,%2,%3}, [%4];"
                 : "=f"(v.x), "=f"(v.y), "=f"(v.z), "=f"(v.w) : "l"(p));
    return v;
}

__global__ void __launch_bounds__(THREADS)
ls_loss_pass1(const float4* __restrict__ inp, const float4* __restrict__ img)
{
    const int b = blockIdx.x;
    const int t = threadIdx.x;
    const long base = (long)b * F4_PER_BLK + t;  // block tiles 1/32 of a channel

    float sH = 0.f, sHI = 0.f, sI = 0.f, sI2 = 0.f;

    #pragma unroll
    for (int g = 0; g < NGRP; g++) {
        float4 x[GRP], m[GRP];
        #pragma unroll
        for (int j = 0; j < GRP; j++) {          // front-batch 8 LDG.128
            const long idx = base + (long)(g * GRP + j) * THREADS;
            x[j] = __ldcs(&inp[idx]);
            m[j] = __ldcs(&img[idx]);
        }
        #pragma unroll
        for (int j = 0; j < GRP; j++) {
            accum1(x[j].x, m[j].x, sH, sHI, sI, sI2);
            accum1(x[j].y, m[j].y, sH, sHI, sI, sI2);
            accum1(x[j].z, m[j].z, sH, sHI, sI, sI2);
            accum1(x[j].w, m[j].w, sH, sHI, sI, sI2);
        }
    }

    // Deterministic warp tree reduce
    #pragma unroll
    for (int o = 16; o > 0; o >>= 1) {
        sH  += __shfl_down_sync(0xFFFFFFFFu, sH,  o);
        sHI += __shfl_down_sync(0xFFFFFFFFu, sHI, o);
        sI  += __shfl_down_sync(0xFFFFFFFFu, sI,  o);
        sI2 += __shfl_down_sync(0xFFFFFFFFu, sI2, o);
    }

    __shared__ float4 sm[THREADS / 32];
    const int warp = t >> 5, lane = t & 31;
    if (lane == 0) sm[warp] = make_float4(sH, sHI, sI, sI2);
    __syncthreads();

    if (t == 0) {
        float4 tot = sm[0];
        #pragma unroll
        for (int w = 1; w < THREADS / 32; w++) {
            float4 v = sm[w];
            tot.x += v.x; tot.y += v.y; tot.z += v.z; tot.w += v.w;
        }
        g_partials[b] = tot;
        __threadfence();                         // publish partial first
        cudaTriggerProgrammaticLaunchCompletion();
    }
}

__global__ void __launch_bounds__(512)
ls_loss_pass2(float* __restrict__ out)
{
    cudaGridDependencySynchronize();   // all pass1 partials published

    const int t = threadIdx.x;
    const int c = t >> 2;              // channel 0..127
    const int q = t & 3;               // quarter within channel

    // Each thread gathers 8 of its channel's 32 partials, front-batched.
    float4 v[8];
    #pragma unroll
    for (int i = 0; i < 8; i++)
        v[i] = ldcg4(&g_partials[c * BLKS_PER_CH + q * 8 + i]);

    float A = 0.f, B1 = 0.f, S = 0.f, Q = 0.f;
    #pragma unroll
    for (int i = 0; i < 8; i++) {
        A += v[i].x; B1 += v[i].y; S += v[i].z; Q += v[i].w;
    }

    // Combine the 4 quarters of each channel (lanes q=0..3 adjacent).
    #pragma unroll
    for (int o = 2; o > 0; o >>= 1) {
        A  += __shfl_down_sync(0xFFFFFFFFu, A,  o);
        B1 += __shfl_down_sync(0xFFFFFFFFu, B1, o);
        S  += __shfl_down_sync(0xFFFFFFFFu, S,  o);
        Q  += __shfl_down_sync(0xFFFFFFFFu, Q,  o);
    }

    __shared__ float s_chan[128];
    if (q == 0) {
        const float Nf = (float)N_PER_CH;
        const float s3 = Nf - A;
        const float c1 = B1 / (A + LS_EPS);
        const float c2 = (S - B1) / (s3 + LS_EPS);
        s_chan[c] = Q - 2.f * (c1 * B1 + c2 * (S - B1))
                  + c1 * c1 * A + c2 * c2 * s3;
    }
    __syncthreads();

    // Fixed-order reduce of the 128 channel values by the first warp.
    if (t < 32) {
        float chan = s_chan[t] + s_chan[t + 32] + s_chan[t + 64] + s_chan[t + 96];
        #pragma unroll
        for (int o = 16; o > 0; o >>= 1)
            chan += __shfl_down_sync(0xFFFFFFFFu, chan, o);
        if (t == 0)
            out[0] = chan / (float)(32 * 4 * N_PER_CH);
    }
}

extern "C" void kernel_launch(void* const* d_in, const int* in_sizes, int n_in,
                              void* d_out, int out_size)
{
    const float4* inp = (const float4*)d_in[0];   // 'input'
    const float4* img = (const float4*)d_in[1];   // 'img_mean'
    float* out = (float*)d_out;

    ls_loss_pass1<<<NBLOCKS, THREADS>>>(inp, img);

    // pass2 via PDL (programmatic serialization); ordered fallback if the
    // Ex-launch path is rejected.
    cudaLaunchConfig_t cfg = {};
    cfg.gridDim  = dim3(1, 1, 1);
    cfg.blockDim = dim3(512, 1, 1);
    cfg.dynamicSmemBytes = 0;
    cfg.stream = 0;
    cudaLaunchAttribute attr[1];
    attr[0].id = cudaLaunchAttributeProgrammaticStreamSerialization;
    attr[0].val.programmaticStreamSerializationAllowed = 1;
    cfg.attrs = attr;
    cfg.numAttrs = 1;
    cudaError_t e = cudaLaunchKernelEx(&cfg, ls_loss_pass2, out);
    if (e != cudaSuccess) {
        (void)cudaGetLastError();
        ls_loss_pass2<<<1, 512>>>(out);
    }
}